// round 15
// baseline (speedup 1.0000x reference)
#include <cuda_runtime.h>
#include <math.h>
#include <stdint.h>

#define NB 16
#define D_NEED 29      // frames d = 31..59
#define D_OFF 31
#define T_NEED 15      // t = 45..59

#define N_OUT (NB * D_NEED * 2500)   // 1,160,000 spatial-conv outputs
#define GRID_A 1184                  // 8 blocks/SM * 148 SMs, perfect waves

// scratch (no allocations allowed)
__device__ float g_s1[NB * D_NEED * 2500];   // spatial-conv output [b][29][50x50]

__device__ __forceinline__ unsigned su32(const void* p) {
    return (unsigned)__cvta_generic_to_shared(p);
}

// ---------------------------------------------------------------------------
// Kernel A: 5x5 stride-5 spatial conv on frames 31..59 — DIRECT, grid-stride.
// 1184 blocks (8/SM exactly), 256 threads; ~4 outputs/thread.
// Fully coalesced; every input byte read once; MLP=25 per output with
// cross-iteration load/FMA overlap; zero barriers -> uniform DRAM demand.
// ---------------------------------------------------------------------------
__global__ void __launch_bounds__(256) kA(const float* __restrict__ x,
                                          const float* __restrict__ sw)
{
    for (int id = blockIdx.x * 256 + threadIdx.x; id < N_OUT;
         id += GRID_A * 256) {
        const int ocol = id % 50;
        const int orow = (id / 50) % 50;
        const int f    = id / 2500;             // 0..463 = b*29 + dIdx
        const int b    = f / D_NEED;
        const int dIdx = f % D_NEED;

        const float* p = x + (size_t)(b * 60 + D_OFF + dIdx) * 62500u
                           + orow * 1250 + ocol * 5;

        float v[25];
        #pragma unroll
        for (int i = 0; i < 5; i++)
            #pragma unroll
            for (int j = 0; j < 5; j++)
                v[i * 5 + j] = __ldg(p + i * 250 + j);

        float a0 = 0.f, a1 = 0.f, a2 = 0.f, a3 = 0.f, a4 = 0.f;
        #pragma unroll
        for (int j = 0; j < 5; j++) {
            a0 = fmaf(sw[0 * 5 + j],  v[0 * 5 + j], a0);
            a1 = fmaf(sw[1 * 5 + j],  v[1 * 5 + j], a1);
            a2 = fmaf(sw[2 * 5 + j],  v[2 * 5 + j], a2);
            a3 = fmaf(sw[3 * 5 + j],  v[3 * 5 + j], a3);
            a4 = fmaf(sw[4 * 5 + j],  v[4 * 5 + j], a4);
        }
        g_s1[id] = ((a0 + a1) + (a2 + a3)) + a4;
    }
    asm volatile("griddepcontrol.launch_dependents;" ::: "memory");
}

// ---------------------------------------------------------------------------
// Kernel BC: temporal conv + ReLU + last conv; cluster of 5 blocks (512 thr,
// 2 row-groups each) per batch gathers the 15x100 flat tile into rank-0's
// smem via DSMEM; rank 0 runs the ama/gang cone -> out[b].
// grid = (5, 16), block = 512, cluster = (5,1,1)  [portable size].
// PDL: weight-load prologue runs before griddepcontrol.wait.
// ---------------------------------------------------------------------------
__global__ void __launch_bounds__(512) __cluster_dims__(5, 1, 1)
kBC(const float* __restrict__ tw_g,
    const float* __restrict__ lw_g,
    const float* __restrict__ acw,
    const float* __restrict__ akw,
    const float* __restrict__ akb,
    const float* __restrict__ alw,
    const float* __restrict__ gcw,
    const float* __restrict__ gkw,
    const float* __restrict__ gkb,
    const float* __restrict__ gcolw,
    float* __restrict__ out)
{
    __shared__ float sfirst[2][T_NEED * 250];  // [sub-group][t][5 rows x 50 cols]
    __shared__ float sflat[T_NEED * 100];      // gather target (used on rank 0)
    __shared__ float tw[15];
    __shared__ float lw[25];
    __shared__ float red[49];
    const int bx  = blockIdx.x;   // cluster rank 0..4
    const int b   = blockIdx.y;
    const int tid = threadIdx.x;

    // -------- prologue: independent of kA's output --------
    if (tid < 15) tw[tid] = tw_g[tid];
    if (tid >= 32 && tid < 57) lw[tid - 32] = lw_g[tid - 32];
    __syncthreads();

    // -------- wait for kA's g_s1 writes --------
    asm volatile("griddepcontrol.wait;" ::: "memory");

    // temporal conv + relu: 500 threads = 2 row-groups x 250 pixel-columns
    if (tid < 500) {
        const int sg  = tid / 250;          // 0..1
        const int col = tid % 250;
        const int grp = bx * 2 + sg;        // row-group 0..9
        const float* src = g_s1 + (size_t)b * (D_NEED * 2500) + grp * 250 + col;
        float v[D_NEED];
        #pragma unroll
        for (int d = 0; d < D_NEED; d++) v[d] = src[d * 2500];
        #pragma unroll
        for (int t = 0; t < T_NEED; t++) {
            float acc = 0.f;
            #pragma unroll
            for (int k = 0; k < 15; k++)
                acc = fmaf(tw[k], v[t + k], acc);
            sfirst[sg][t * 250 + col] = fmaxf(acc, 0.f);
        }
    }
    __syncthreads();

    // last conv -> DSMEM store into rank 0's sflat (300 threads: 2 x 15 x 10)
    if (tid < 300) {
        const int sg  = tid / 150;
        const int r   = tid % 150;
        const int t   = r / 10, c = r % 10;
        const int grp = bx * 2 + sg;
        const float* p = &sfirst[sg][t * 250 + c * 5];
        float acc = 0.f;
        #pragma unroll
        for (int i = 0; i < 5; i++)
            #pragma unroll
            for (int j = 0; j < 5; j++)
                acc = fmaf(lw[i * 5 + j], p[i * 50 + j], acc);

        unsigned laddr = su32(&sflat[t * 100 + grp * 10 + c]);
        unsigned raddr;
        asm volatile("mapa.shared::cluster.u32 %0, %1, 0;"
                     : "=r"(raddr) : "r"(laddr));
        asm volatile("st.shared::cluster.f32 [%0], %1;"
                     :: "r"(raddr), "f"(acc) : "memory");
    }

    // cluster barrier: all DSMEM stores visible to rank 0 afterwards
    asm volatile("barrier.cluster.arrive.aligned;" ::: "memory");
    asm volatile("barrier.cluster.wait.aligned;"   ::: "memory");

    if (bx != 0) return;

    // ---- rank 0: ama/gang cone at t=59 + 49-tap dot ----
    if (tid < 49) {
        const float ac = acw[0], al = alw[0], gc = gcw[0];
        const int ja = 2 * tid;
        const int jg = (2 * tid + 25) % 100;
        float a = akb[0];
        float g = gkb[0];
        #pragma unroll
        for (int k = 0; k < 15; k++) {
            a = fmaf(akw[k], ac * sflat[k * 100 + ja], a);
            g = fmaf(gkw[k], gc * sflat[k * 100 + jg], g);
        }
        const float amo = al / (1.f + expf(-a));
        const float val = 1.f / (1.f + expf(-(g - fabsf(amo))));
        red[tid] = gcolw[tid] * val;
    }
    __syncthreads();

    if (tid == 0) {
        float s = 0.f;
        #pragma unroll
        for (int j = 0; j < 49; j++) s += red[j];
        out[b] = s;
    }
}

// ---------------------------------------------------------------------------
extern "C" void kernel_launch(void* const* d_in, const int* in_sizes, int n_in,
                              void* d_out, int out_size)
{
    const float* x          = (const float*)d_in[0];
    const float* space_w    = (const float*)d_in[1];
    const float* temporal_w = (const float*)d_in[2];
    const float* last_w     = (const float*)d_in[3];
    const float* ama_create = (const float*)d_in[4];
    const float* ama_kern   = (const float*)d_in[5];
    const float* ama_kern_b = (const float*)d_in[6];
    const float* ama_alpha  = (const float*)d_in[7];
    const float* gang_create= (const float*)d_in[8];
    const float* gang_kern  = (const float*)d_in[9];
    const float* gang_kern_b= (const float*)d_in[10];
    const float* gang_col   = (const float*)d_in[11];
    float* out = (float*)d_out;

    kA<<<GRID_A, 256>>>(x, space_w);

    // PDL launch of kBC: overlaps its prologue with kA's drain
    cudaLaunchConfig_t cfg = {};
    cfg.gridDim  = dim3(5, NB);
    cfg.blockDim = dim3(512);
    cudaLaunchAttribute attrs[1];
    attrs[0].id = cudaLaunchAttributeProgrammaticStreamSerialization;
    attrs[0].val.programmaticStreamSerializationAllowed = 1;
    cfg.attrs = attrs;
    cfg.numAttrs = 1;
    cudaLaunchKernelEx(&cfg, kBC, temporal_w, last_w,
                       ama_create, ama_kern, ama_kern_b, ama_alpha,
                       gang_create, gang_kern, gang_kern_b, gang_col, out);
}

// round 16
// speedup vs baseline: 1.0801x; 1.0801x over previous
#include <cuda_runtime.h>
#include <math.h>
#include <stdint.h>

#define NB 16
#define D_NEED 29      // frames d = 31..59
#define D_OFF 31
#define T_NEED 15      // t = 45..59

#define N_OUT (NB * D_NEED * 2500)   // 1,160,000 spatial-conv outputs

// scratch (no allocations allowed)
__device__ float g_s1[NB * D_NEED * 2500];   // spatial-conv output [b][29][50x50]

__device__ __forceinline__ unsigned su32(const void* p) {
    return (unsigned)__cvta_generic_to_shared(p);
}

// ---------------------------------------------------------------------------
// Kernel A: 5x5 stride-5 spatial conv on frames 31..59 — DIRECT, no smem.
// 1 thread = 1 output pixel; fully coalesced; every input byte read once
// (streaming .cs hint: keep L2 for g_s1); MLP=25 per thread; zero barriers.
// Executes griddepcontrol.launch_dependents after its store (PDL).
// ---------------------------------------------------------------------------
__global__ void __launch_bounds__(256) kA(const float* __restrict__ x,
                                          const float* __restrict__ sw)
{
    const int id = blockIdx.x * 256 + threadIdx.x;
    if (id < N_OUT) {
        const int ocol = id % 50;
        const int orow = (id / 50) % 50;
        const int f    = id / 2500;             // 0..463 = b*29 + dIdx
        const int b    = f / D_NEED;
        const int dIdx = f % D_NEED;

        const float* p = x + (size_t)(b * 60 + D_OFF + dIdx) * 62500u
                           + orow * 1250 + ocol * 5;

        float v[25];
        #pragma unroll
        for (int i = 0; i < 5; i++)
            #pragma unroll
            for (int j = 0; j < 5; j++)
                v[i * 5 + j] = __ldcs(p + i * 250 + j);

        float a0 = 0.f, a1 = 0.f, a2 = 0.f, a3 = 0.f, a4 = 0.f;
        #pragma unroll
        for (int j = 0; j < 5; j++) {
            a0 = fmaf(sw[0 * 5 + j],  v[0 * 5 + j], a0);
            a1 = fmaf(sw[1 * 5 + j],  v[1 * 5 + j], a1);
            a2 = fmaf(sw[2 * 5 + j],  v[2 * 5 + j], a2);
            a3 = fmaf(sw[3 * 5 + j],  v[3 * 5 + j], a3);
            a4 = fmaf(sw[4 * 5 + j],  v[4 * 5 + j], a4);
        }
        g_s1[id] = ((a0 + a1) + (a2 + a3)) + a4;
    }
    asm volatile("griddepcontrol.launch_dependents;" ::: "memory");
}

// ---------------------------------------------------------------------------
// Kernel BC: temporal conv + ReLU + last conv, then a CLUSTER (10 blocks =
// one batch) gathers the 15x100 flat tile into rank-0's smem via DSMEM
// stores; after cluster.sync rank 0 runs the ama/gang cone -> out[b].
// grid = (10, 16), block = 256, cluster = (10,1,1)  [non-portable size].
// PDL: prologue (weight loads) runs before griddepcontrol.wait, overlapping
// kA's tail; g_s1 is only read after the wait.
// ---------------------------------------------------------------------------
__global__ void __launch_bounds__(256) __cluster_dims__(10, 1, 1)
kBC(const float* __restrict__ tw_g,
    const float* __restrict__ lw_g,
    const float* __restrict__ acw,
    const float* __restrict__ akw,
    const float* __restrict__ akb,
    const float* __restrict__ alw,
    const float* __restrict__ gcw,
    const float* __restrict__ gkw,
    const float* __restrict__ gkb,
    const float* __restrict__ gcolw,
    float* __restrict__ out)
{
    __shared__ float sfirst[T_NEED * 250];   // [t][5 rows x 50 cols]
    __shared__ float sflat[T_NEED * 100];    // gather target (used on rank 0)
    __shared__ float tw[15];
    __shared__ float lw[25];
    __shared__ float red[49];
    const int grp = blockIdx.x;   // row-group == cluster rank
    const int b   = blockIdx.y;
    const int tid = threadIdx.x;

    // -------- prologue: independent of kA's output --------
    if (tid < 15) tw[tid] = tw_g[tid];
    if (tid >= 32 && tid < 57) lw[tid - 32] = lw_g[tid - 32];
    __syncthreads();

    // -------- wait for kA's g_s1 writes --------
    asm volatile("griddepcontrol.wait;" ::: "memory");

    // temporal conv + relu (g_s1 read exactly once, coalesced)
    if (tid < 250) {
        const float* src = g_s1 + (size_t)b * (D_NEED * 2500) + grp * 250 + tid;
        float v[D_NEED];
        #pragma unroll
        for (int d = 0; d < D_NEED; d++) v[d] = src[d * 2500];
        #pragma unroll
        for (int t = 0; t < T_NEED; t++) {
            float acc = 0.f;
            #pragma unroll
            for (int k = 0; k < 15; k++)
                acc = fmaf(tw[k], v[t + k], acc);
            sfirst[t * 250 + tid] = fmaxf(acc, 0.f);
        }
    }
    __syncthreads();

    // last conv -> DSMEM store into rank 0's sflat
    if (tid < 150) {
        const int t = tid / 10, c = tid % 10;
        const float* p = sfirst + t * 250 + c * 5;
        float acc = 0.f;
        #pragma unroll
        for (int i = 0; i < 5; i++)
            #pragma unroll
            for (int j = 0; j < 5; j++)
                acc = fmaf(lw[i * 5 + j], p[i * 50 + j], acc);

        unsigned laddr = su32(&sflat[t * 100 + grp * 10 + c]);
        unsigned raddr;
        asm volatile("mapa.shared::cluster.u32 %0, %1, 0;"
                     : "=r"(raddr) : "r"(laddr));
        asm volatile("st.shared::cluster.f32 [%0], %1;"
                     :: "r"(raddr), "f"(acc) : "memory");
    }

    // cluster barrier: all DSMEM stores visible to rank 0 afterwards
    asm volatile("barrier.cluster.arrive.aligned;" ::: "memory");
    asm volatile("barrier.cluster.wait.aligned;"   ::: "memory");

    if (grp != 0) return;

    // ---- rank 0: ama/gang cone at t=59 + 49-tap dot ----
    if (tid < 49) {
        const float ac = acw[0], al = alw[0], gc = gcw[0];
        const int ja = 2 * tid;
        const int jg = (2 * tid + 25) % 100;
        float a = akb[0];
        float g = gkb[0];
        #pragma unroll
        for (int k = 0; k < 15; k++) {
            a = fmaf(akw[k], ac * sflat[k * 100 + ja], a);
            g = fmaf(gkw[k], gc * sflat[k * 100 + jg], g);
        }
        const float amo = al / (1.f + expf(-a));
        const float val = 1.f / (1.f + expf(-(g - fabsf(amo))));
        red[tid] = gcolw[tid] * val;
    }
    __syncthreads();

    if (tid == 0) {
        float s = 0.f;
        #pragma unroll
        for (int j = 0; j < 49; j++) s += red[j];
        out[b] = s;
    }
}

// ---------------------------------------------------------------------------
extern "C" void kernel_launch(void* const* d_in, const int* in_sizes, int n_in,
                              void* d_out, int out_size)
{
    const float* x          = (const float*)d_in[0];
    const float* space_w    = (const float*)d_in[1];
    const float* temporal_w = (const float*)d_in[2];
    const float* last_w     = (const float*)d_in[3];
    const float* ama_create = (const float*)d_in[4];
    const float* ama_kern   = (const float*)d_in[5];
    const float* ama_kern_b = (const float*)d_in[6];
    const float* ama_alpha  = (const float*)d_in[7];
    const float* gang_create= (const float*)d_in[8];
    const float* gang_kern  = (const float*)d_in[9];
    const float* gang_kern_b= (const float*)d_in[10];
    const float* gang_col   = (const float*)d_in[11];
    float* out = (float*)d_out;

    // cluster size 10 > 8 -> non-portable cluster size must be allowed
    cudaFuncSetAttribute(kBC, cudaFuncAttributeNonPortableClusterSizeAllowed, 1);

    kA<<<(N_OUT + 255) / 256, 256>>>(x, space_w);

    // PDL launch of kBC: overlaps its prologue with kA's drain
    cudaLaunchConfig_t cfg = {};
    cfg.gridDim  = dim3(10, NB);
    cfg.blockDim = dim3(256);
    cudaLaunchAttribute attrs[1];
    attrs[0].id = cudaLaunchAttributeProgrammaticStreamSerialization;
    attrs[0].val.programmaticStreamSerializationAllowed = 1;
    cfg.attrs = attrs;
    cfg.numAttrs = 1;
    cudaLaunchKernelEx(&cfg, kBC, temporal_w, last_w,
                       ama_create, ama_kern, ama_kern_b, ama_alpha,
                       gang_create, gang_kern, gang_kern_b, gang_col, out);
}

// round 17
// speedup vs baseline: 1.0945x; 1.0133x over previous
#include <cuda_runtime.h>
#include <math.h>
#include <stdint.h>

#define NB 16
#define D_NEED 29      // frames d = 31..59
#define D_OFF 31
#define T_NEED 15      // t = 45..59

#define N_OUT (NB * D_NEED * 2500)   // 1,160,000 spatial-conv outputs

// scratch (no allocations allowed)
__device__ float g_s1[NB * D_NEED * 2500];   // spatial-conv output [b][29][50x50]

__device__ __forceinline__ unsigned su32(const void* p) {
    return (unsigned)__cvta_generic_to_shared(p);
}

// ---------------------------------------------------------------------------
// Kernel A: 5x5 stride-5 spatial conv on frames 31..59 — DIRECT, no smem.
// 1 thread = 1 output pixel; fully coalesced; every input byte read once;
// MLP=25 per thread; zero barriers -> uniform DRAM demand (~5.3 TB/s, the
// measured path-independent achieved-BW ceiling on this chip).
// Executes griddepcontrol.launch_dependents after its store (PDL).
// ---------------------------------------------------------------------------
__global__ void __launch_bounds__(256) kA(const float* __restrict__ x,
                                          const float* __restrict__ sw)
{
    const int id = blockIdx.x * 256 + threadIdx.x;
    if (id < N_OUT) {
        const int ocol = id % 50;
        const int orow = (id / 50) % 50;
        const int f    = id / 2500;             // 0..463 = b*29 + dIdx
        const int b    = f / D_NEED;
        const int dIdx = f % D_NEED;

        const float* p = x + (size_t)(b * 60 + D_OFF + dIdx) * 62500u
                           + orow * 1250 + ocol * 5;

        float v[25];
        #pragma unroll
        for (int i = 0; i < 5; i++)
            #pragma unroll
            for (int j = 0; j < 5; j++)
                v[i * 5 + j] = __ldg(p + i * 250 + j);

        float a0 = 0.f, a1 = 0.f, a2 = 0.f, a3 = 0.f, a4 = 0.f;
        #pragma unroll
        for (int j = 0; j < 5; j++) {
            a0 = fmaf(sw[0 * 5 + j],  v[0 * 5 + j], a0);
            a1 = fmaf(sw[1 * 5 + j],  v[1 * 5 + j], a1);
            a2 = fmaf(sw[2 * 5 + j],  v[2 * 5 + j], a2);
            a3 = fmaf(sw[3 * 5 + j],  v[3 * 5 + j], a3);
            a4 = fmaf(sw[4 * 5 + j],  v[4 * 5 + j], a4);
        }
        g_s1[id] = ((a0 + a1) + (a2 + a3)) + a4;
    }
    asm volatile("griddepcontrol.launch_dependents;" ::: "memory");
}

// ---------------------------------------------------------------------------
// Kernel BC: temporal conv + ReLU + last conv, then a CLUSTER (10 blocks =
// one batch) gathers the 15x100 flat tile into rank-0's smem via DSMEM
// stores; after cluster.sync rank 0 runs the ama/gang cone -> out[b].
// grid = (10, 16), block = 256, cluster = (10,1,1)  [non-portable size].
// PDL: prologue (weight loads) runs before griddepcontrol.wait, overlapping
// kA's tail; g_s1 is only read after the wait.
// ---------------------------------------------------------------------------
__global__ void __launch_bounds__(256) __cluster_dims__(10, 1, 1)
kBC(const float* __restrict__ tw_g,
    const float* __restrict__ lw_g,
    const float* __restrict__ acw,
    const float* __restrict__ akw,
    const float* __restrict__ akb,
    const float* __restrict__ alw,
    const float* __restrict__ gcw,
    const float* __restrict__ gkw,
    const float* __restrict__ gkb,
    const float* __restrict__ gcolw,
    float* __restrict__ out)
{
    __shared__ float sfirst[T_NEED * 250];   // [t][5 rows x 50 cols]
    __shared__ float sflat[T_NEED * 100];    // gather target (used on rank 0)
    __shared__ float tw[15];
    __shared__ float lw[25];
    __shared__ float red[49];
    const int grp = blockIdx.x;   // row-group == cluster rank
    const int b   = blockIdx.y;
    const int tid = threadIdx.x;

    // -------- prologue: independent of kA's output --------
    if (tid < 15) tw[tid] = tw_g[tid];
    if (tid >= 32 && tid < 57) lw[tid - 32] = lw_g[tid - 32];
    __syncthreads();

    // -------- wait for kA's g_s1 writes --------
    asm volatile("griddepcontrol.wait;" ::: "memory");

    // temporal conv + relu (g_s1 read exactly once, coalesced, L2-hot)
    if (tid < 250) {
        const float* src = g_s1 + (size_t)b * (D_NEED * 2500) + grp * 250 + tid;
        float v[D_NEED];
        #pragma unroll
        for (int d = 0; d < D_NEED; d++) v[d] = src[d * 2500];
        #pragma unroll
        for (int t = 0; t < T_NEED; t++) {
            float acc = 0.f;
            #pragma unroll
            for (int k = 0; k < 15; k++)
                acc = fmaf(tw[k], v[t + k], acc);
            sfirst[t * 250 + tid] = fmaxf(acc, 0.f);
        }
    }
    __syncthreads();

    // last conv -> DSMEM store into rank 0's sflat
    if (tid < 150) {
        const int t = tid / 10, c = tid % 10;
        const float* p = sfirst + t * 250 + c * 5;
        float acc = 0.f;
        #pragma unroll
        for (int i = 0; i < 5; i++)
            #pragma unroll
            for (int j = 0; j < 5; j++)
                acc = fmaf(lw[i * 5 + j], p[i * 50 + j], acc);

        unsigned laddr = su32(&sflat[t * 100 + grp * 10 + c]);
        unsigned raddr;
        asm volatile("mapa.shared::cluster.u32 %0, %1, 0;"
                     : "=r"(raddr) : "r"(laddr));
        asm volatile("st.shared::cluster.f32 [%0], %1;"
                     :: "r"(raddr), "f"(acc) : "memory");
    }

    // cluster barrier: all DSMEM stores visible to rank 0 afterwards
    asm volatile("barrier.cluster.arrive.aligned;" ::: "memory");
    asm volatile("barrier.cluster.wait.aligned;"   ::: "memory");

    if (grp != 0) return;

    // ---- rank 0: ama/gang cone at t=59 + 49-tap dot ----
    if (tid < 49) {
        const float ac = acw[0], al = alw[0], gc = gcw[0];
        const int ja = 2 * tid;
        const int jg = (2 * tid + 25) % 100;
        float a = akb[0];
        float g = gkb[0];
        #pragma unroll
        for (int k = 0; k < 15; k++) {
            a = fmaf(akw[k], ac * sflat[k * 100 + ja], a);
            g = fmaf(gkw[k], gc * sflat[k * 100 + jg], g);
        }
        const float amo = al / (1.f + expf(-a));
        const float val = 1.f / (1.f + expf(-(g - fabsf(amo))));
        red[tid] = gcolw[tid] * val;
    }
    __syncthreads();

    if (tid == 0) {
        float s = 0.f;
        #pragma unroll
        for (int j = 0; j < 49; j++) s += red[j];
        out[b] = s;
    }
}

// ---------------------------------------------------------------------------
extern "C" void kernel_launch(void* const* d_in, const int* in_sizes, int n_in,
                              void* d_out, int out_size)
{
    const float* x          = (const float*)d_in[0];
    const float* space_w    = (const float*)d_in[1];
    const float* temporal_w = (const float*)d_in[2];
    const float* last_w     = (const float*)d_in[3];
    const float* ama_create = (const float*)d_in[4];
    const float* ama_kern   = (const float*)d_in[5];
    const float* ama_kern_b = (const float*)d_in[6];
    const float* ama_alpha  = (const float*)d_in[7];
    const float* gang_create= (const float*)d_in[8];
    const float* gang_kern  = (const float*)d_in[9];
    const float* gang_kern_b= (const float*)d_in[10];
    const float* gang_col   = (const float*)d_in[11];
    float* out = (float*)d_out;

    // cluster size 10 > 8 -> non-portable cluster size must be allowed
    cudaFuncSetAttribute(kBC, cudaFuncAttributeNonPortableClusterSizeAllowed, 1);

    kA<<<(N_OUT + 255) / 256, 256>>>(x, space_w);

    // PDL launch of kBC: overlaps its prologue with kA's drain
    cudaLaunchConfig_t cfg = {};
    cfg.gridDim  = dim3(10, NB);
    cfg.blockDim = dim3(256);
    cudaLaunchAttribute attrs[1];
    attrs[0].id = cudaLaunchAttributeProgrammaticStreamSerialization;
    attrs[0].val.programmaticStreamSerializationAllowed = 1;
    cfg.attrs = attrs;
    cfg.numAttrs = 1;
    cudaLaunchKernelEx(&cfg, kBC, temporal_w, last_w,
                       ama_create, ama_kern, ama_kern_b, ama_alpha,
                       gang_create, gang_kern, gang_kern_b, gang_col, out);
}